// round 14
// baseline (speedup 1.0000x reference)
#include <cuda_runtime.h>
#include <cuda_fp16.h>
#include <math.h>

#define NMAX   50000
#define EMAX   800000
#define ETMAX  (EMAX + NMAX)
#define IN_C   128
#define HID    16
#define HEADS  8
#define H1C    (HEADS * HID)   // 128
#define OUT_C  64
#define NEG    0.2f

// ---------------- scratch (device globals; no allocation allowed) ----------
__device__ uint2 g_H1h[(size_t)NMAX * 32];     // layer1 features, fp16 (4/lane)
__device__ uint  g_H2h[(size_t)NMAX * 32];     // layer2 features, fp16 (2/lane)
__device__ float g_OUT1[(size_t)NMAX * H1C];   // layer1 output (post relu, fp32)
__device__ float g_al1s[NMAX * HEADS];
__device__ float g_al1d[NMAX * HEADS];
__device__ float g_al2s[NMAX];
__device__ float g_al2d[NMAX];
__device__ int   g_rowptr[NMAX + 1];
__device__ int   g_cnt[NMAX];                  // counts, then write cursors
__device__ int   g_esrc[ETMAX];                // src node per (dst-sorted) edge

// ---------------- CSR build ------------------------------------------------
__global__ void count_kernel(const int* __restrict__ ei, int E, int ET) {
    int i = blockIdx.x * blockDim.x + threadIdx.x;
    if (i >= ET) return;
    int dst = (i < E) ? ei[E + i] : (i - E);   // self loops appended
    atomicAdd(&g_cnt[dst], 1);
}

// single-block scan, 2 barriers: serial partials + two-level shuffle scan
__global__ void scan_kernel(int n) {
    const int T = 1024;
    __shared__ int wsum[32];
    int t = threadIdx.x, lane = t & 31, wid = t >> 5;
    int C = (n + T - 1) / T;
    int beg = t * C;
    int end = beg + C; if (end > n) end = n;

    int sum = 0;
    for (int i = beg; i < end; i++) sum += g_cnt[i];

    int incl = sum;
#pragma unroll
    for (int off = 1; off < 32; off <<= 1) {
        int v = __shfl_up_sync(0xffffffffu, incl, off);
        if (lane >= off) incl += v;
    }
    if (lane == 31) wsum[wid] = incl;
    __syncthreads();
    if (wid == 0) {
        int w = wsum[lane];
        int wi = w;
#pragma unroll
        for (int off = 1; off < 32; off <<= 1) {
            int v = __shfl_up_sync(0xffffffffu, wi, off);
            if (lane >= off) wi += v;
        }
        wsum[lane] = wi - w;
    }
    __syncthreads();

    int run = wsum[wid] + (incl - sum);
    for (int i = beg; i < end; i++) {
        int c = g_cnt[i];
        g_rowptr[i] = run;
        g_cnt[i]    = run;
        run += c;
    }
    if (beg < n && end == n) g_rowptr[n] = run;
}

__global__ void scatter_kernel(const int* __restrict__ ei, int E, int ET) {
    int i = blockIdx.x * blockDim.x + threadIdx.x;
    if (i >= ET) return;
    int src, dst;
    if (i < E) { src = ei[i]; dst = ei[E + i]; }
    else       { src = i - E; dst = i - E; }
    int pos = atomicAdd(&g_cnt[dst], 1);
    g_esrc[pos] = src;
}

// ---------------- GEMM1: X @ W1 -> fp16 H1 + fused al1 logits --------------
// 512 thr, 64 rows x 128 cols per block. smem 96KB -> 2 blocks/SM (32 warps).
__global__ __launch_bounds__(512, 2) void gemm1_kernel(
        const float* __restrict__ X, const float* __restrict__ W,
        const float* __restrict__ a1s, const float* __restrict__ a1d, int M) {
    extern __shared__ float smem[];
    float4* Wsh = (float4*)smem;           // 128 * 32 float4 = 64 KB
    float*  Xsh = smem + 128 * 128;        // 64 * 128 floats = 32 KB
    int tid = threadIdx.x;

    const float4* W4 = (const float4*)W;
    for (int i = tid; i < 128 * 32; i += 512) Wsh[i] = W4[i];

    int row0 = blockIdx.x * 64;
    for (int i = tid; i < 64 * 32; i += 512) {
        int r = i >> 5, kc = i & 31;
        float4 v = make_float4(0.f, 0.f, 0.f, 0.f);
        if (row0 + r < M) v = ((const float4*)X)[(size_t)(row0 + r) * 32 + kc];
        *(float4*)&Xsh[r * 128 + kc * 4] = v;
    }
    __syncthreads();

    int tx = tid & 31, ty = tid >> 5;      // warp == ty
    float4 acc[4];
#pragma unroll
    for (int r = 0; r < 4; r++) acc[r] = make_float4(0.f, 0.f, 0.f, 0.f);

    for (int k4 = 0; k4 < 32; k4++) {
        float4 wv0 = Wsh[(k4 * 4 + 0) * 32 + tx];
        float4 wv1 = Wsh[(k4 * 4 + 1) * 32 + tx];
        float4 wv2 = Wsh[(k4 * 4 + 2) * 32 + tx];
        float4 wv3 = Wsh[(k4 * 4 + 3) * 32 + tx];
#pragma unroll
        for (int r = 0; r < 4; r++) {
            float4 xv = *(const float4*)&Xsh[(ty * 4 + r) * 128 + k4 * 4];
            acc[r].x += xv.x * wv0.x + xv.y * wv1.x + xv.z * wv2.x + xv.w * wv3.x;
            acc[r].y += xv.x * wv0.y + xv.y * wv1.y + xv.z * wv2.y + xv.w * wv3.y;
            acc[r].z += xv.x * wv0.z + xv.y * wv1.z + xv.z * wv2.z + xv.w * wv3.z;
            acc[r].w += xv.x * wv0.w + xv.y * wv1.w + xv.z * wv2.w + xv.w * wv3.w;
        }
    }

    float4 as = ((const float4*)a1s)[tx];
    float4 ad = ((const float4*)a1d)[tx];
    int head = tx >> 2;
#pragma unroll
    for (int r = 0; r < 4; r++) {
        int row = row0 + ty * 4 + r;
        if (row < M) {
            __half2 h01 = __floats2half2_rn(acc[r].x, acc[r].y);
            __half2 h23 = __floats2half2_rn(acc[r].z, acc[r].w);
            uint2 pk;
            pk.x = *reinterpret_cast<unsigned*>(&h01);
            pk.y = *reinterpret_cast<unsigned*>(&h23);
            g_H1h[(size_t)row * 32 + tx] = pk;
            float ps = acc[r].x * as.x + acc[r].y * as.y + acc[r].z * as.z + acc[r].w * as.w;
            float pd = acc[r].x * ad.x + acc[r].y * ad.y + acc[r].z * ad.z + acc[r].w * ad.w;
            ps += __shfl_xor_sync(0xffffffffu, ps, 1);
            ps += __shfl_xor_sync(0xffffffffu, ps, 2);
            pd += __shfl_xor_sync(0xffffffffu, pd, 1);
            pd += __shfl_xor_sync(0xffffffffu, pd, 2);
            if ((tx & 3) == 0) {
                g_al1s[row * 8 + head] = ps;
                g_al1d[row * 8 + head] = pd;
            }
        }
    }
}

// ---------------- GEMM2: OUT1 @ W2 -> fp16 H2 + fused al2 logits -----------
__global__ __launch_bounds__(512, 2) void gemm2_kernel(
        const float* __restrict__ X, const float* __restrict__ W,
        const float* __restrict__ a2s, const float* __restrict__ a2d, int M) {
    extern __shared__ float smem[];
    float4* Wsh = (float4*)smem;           // 128 * 16 float4 = 32 KB
    float*  Xsh = smem + 128 * 64;         // 64 * 128 floats = 32 KB
    int tid = threadIdx.x;

    const float4* W4 = (const float4*)W;
    for (int i = tid; i < 128 * 16; i += 512) Wsh[i] = W4[i];

    int row0 = blockIdx.x * 64;
    for (int i = tid; i < 64 * 32; i += 512) {
        int r = i >> 5, kc = i & 31;
        float4 v = make_float4(0.f, 0.f, 0.f, 0.f);
        if (row0 + r < M) v = ((const float4*)X)[(size_t)(row0 + r) * 32 + kc];
        *(float4*)&Xsh[r * 128 + kc * 4] = v;
    }
    __syncthreads();

    int tx = tid & 15, ty = tid >> 4;
    float4 acc[2];
#pragma unroll
    for (int r = 0; r < 2; r++) acc[r] = make_float4(0.f, 0.f, 0.f, 0.f);

    for (int k4 = 0; k4 < 32; k4++) {
        float4 wv0 = Wsh[(k4 * 4 + 0) * 16 + tx];
        float4 wv1 = Wsh[(k4 * 4 + 1) * 16 + tx];
        float4 wv2 = Wsh[(k4 * 4 + 2) * 16 + tx];
        float4 wv3 = Wsh[(k4 * 4 + 3) * 16 + tx];
#pragma unroll
        for (int r = 0; r < 2; r++) {
            float4 xv = *(const float4*)&Xsh[(ty * 2 + r) * 128 + k4 * 4];
            acc[r].x += xv.x * wv0.x + xv.y * wv1.x + xv.z * wv2.x + xv.w * wv3.x;
            acc[r].y += xv.x * wv0.y + xv.y * wv1.y + xv.z * wv2.y + xv.w * wv3.y;
            acc[r].z += xv.x * wv0.z + xv.y * wv1.z + xv.z * wv2.z + xv.w * wv3.z;
            acc[r].w += xv.x * wv0.w + xv.y * wv1.w + xv.z * wv2.w + xv.w * wv3.w;
        }
    }

    float4 as = ((const float4*)a2s)[tx];
    float4 ad = ((const float4*)a2d)[tx];
#pragma unroll
    for (int r = 0; r < 2; r++) {
        int row = row0 + ty * 2 + r;
        if (row < M) {
            __half2 h01 = __floats2half2_rn(acc[r].x, acc[r].y);
            __half2 h23 = __floats2half2_rn(acc[r].z, acc[r].w);
            g_H2h[(size_t)row * 32 + 2 * tx]     = *reinterpret_cast<unsigned*>(&h01);
            g_H2h[(size_t)row * 32 + 2 * tx + 1] = *reinterpret_cast<unsigned*>(&h23);
            float ps = acc[r].x * as.x + acc[r].y * as.y + acc[r].z * as.z + acc[r].w * as.w;
            float pd = acc[r].x * ad.x + acc[r].y * ad.y + acc[r].z * ad.z + acc[r].w * ad.w;
#pragma unroll
            for (int off = 8; off >= 1; off >>= 1) {
                ps += __shfl_xor_sync(0xffffffffu, ps, off);
                pd += __shfl_xor_sync(0xffffffffu, pd, off);
            }
            if (tx == 0) { g_al2s[row] = ps; g_al2d[row] = pd; }
        }
    }
}

// ---------------- aggregation: single pass, pairwise (MLP=2), fp16 gathers -
// Logits are O(1): exp without max subtraction is overflow-safe and exact.
__global__ void agg1_kernel(const float* __restrict__ b1, int n) {
    int node = (blockIdx.x * blockDim.x + threadIdx.x) >> 5;
    int lane = threadIdx.x & 31;
    if (node >= n) return;
    int beg = g_rowptr[node], end = g_rowptr[node + 1];
    float ald = (lane < 8) ? g_al1d[node * 8 + lane] : 0.f;
    int head = lane >> 2;

    float denom = 0.f;
    float4 acc = make_float4(0.f, 0.f, 0.f, 0.f);

    int sA = (beg     < end) ? g_esrc[beg]     : 0;
    int sB = (beg + 1 < end) ? g_esrc[beg + 1] : 0;
    int j = beg;
    for (; j + 1 < end; j += 2) {
        int sC = (j + 2 < end) ? g_esrc[j + 2] : 0;
        int sD = (j + 3 < end) ? g_esrc[j + 3] : 0;
        uint2 pA = g_H1h[(size_t)sA * 32 + lane];
        uint2 pB = g_H1h[(size_t)sB * 32 + lane];
        float eeA = 0.f, eeB = 0.f;
        if (lane < 8) {
            float lA = g_al1s[sA * 8 + lane];
            float lB = g_al1s[sB * 8 + lane];
            float eA = lA + ald; eA = (eA > 0.f) ? eA : NEG * eA;
            float eB = lB + ald; eB = (eB > 0.f) ? eB : NEG * eB;
            eeA = __expf(eA); eeB = __expf(eB);
            denom += eeA + eeB;
        }
        float wA = __shfl_sync(0xffffffffu, eeA, head);
        float wB = __shfl_sync(0xffffffffu, eeB, head);
        float2 a01 = __half22float2(*reinterpret_cast<__half2*>(&pA.x));
        float2 a23 = __half22float2(*reinterpret_cast<__half2*>(&pA.y));
        float2 b01 = __half22float2(*reinterpret_cast<__half2*>(&pB.x));
        float2 b23 = __half22float2(*reinterpret_cast<__half2*>(&pB.y));
        acc.x += wA * a01.x + wB * b01.x;
        acc.y += wA * a01.y + wB * b01.y;
        acc.z += wA * a23.x + wB * b23.x;
        acc.w += wA * a23.y + wB * b23.y;
        sA = sC; sB = sD;
    }
    if (j < end) {   // odd tail: sA holds esrc[j]
        uint2 pA = g_H1h[(size_t)sA * 32 + lane];
        float eeA = 0.f;
        if (lane < 8) {
            float eA = g_al1s[sA * 8 + lane] + ald;
            eA = (eA > 0.f) ? eA : NEG * eA;
            eeA = __expf(eA);
            denom += eeA;
        }
        float wA = __shfl_sync(0xffffffffu, eeA, head);
        float2 a01 = __half22float2(*reinterpret_cast<__half2*>(&pA.x));
        float2 a23 = __half22float2(*reinterpret_cast<__half2*>(&pA.y));
        acc.x += wA * a01.x; acc.y += wA * a01.y;
        acc.z += wA * a23.x; acc.w += wA * a23.y;
    }

    float dh  = __shfl_sync(0xffffffffu, denom, head);
    float inv = 1.f / (dh + 1e-16f);
    float4 b = ((const float4*)b1)[lane];
    float4 o;
    o.x = fmaxf(acc.x * inv + b.x, 0.f);
    o.y = fmaxf(acc.y * inv + b.y, 0.f);
    o.z = fmaxf(acc.z * inv + b.z, 0.f);
    o.w = fmaxf(acc.w * inv + b.w, 0.f);
    *(float4*)&g_OUT1[(size_t)node * 128 + lane * 4] = o;
}

__global__ void agg2_kernel(const float* __restrict__ b2,
                            float* __restrict__ out, int n) {
    int node = (blockIdx.x * blockDim.x + threadIdx.x) >> 5;
    int lane = threadIdx.x & 31;
    if (node >= n) return;
    int beg = g_rowptr[node], end = g_rowptr[node + 1];
    float ald = g_al2d[node];

    float denom = 0.f;
    float2 acc = make_float2(0.f, 0.f);

    int sA = (beg     < end) ? g_esrc[beg]     : 0;
    int sB = (beg + 1 < end) ? g_esrc[beg + 1] : 0;
    int j = beg;
    for (; j + 1 < end; j += 2) {
        int sC = (j + 2 < end) ? g_esrc[j + 2] : 0;
        int sD = (j + 3 < end) ? g_esrc[j + 3] : 0;
        unsigned pA = g_H2h[(size_t)sA * 32 + lane];
        unsigned pB = g_H2h[(size_t)sB * 32 + lane];
        float eA = g_al2s[sA] + ald; eA = (eA > 0.f) ? eA : NEG * eA;
        float eB = g_al2s[sB] + ald; eB = (eB > 0.f) ? eB : NEG * eB;
        float eeA = __expf(eA), eeB = __expf(eB);
        denom += eeA + eeB;
        float2 vA = __half22float2(*reinterpret_cast<__half2*>(&pA));
        float2 vB = __half22float2(*reinterpret_cast<__half2*>(&pB));
        acc.x += eeA * vA.x + eeB * vB.x;
        acc.y += eeA * vA.y + eeB * vB.y;
        sA = sC; sB = sD;
    }
    if (j < end) {
        unsigned pA = g_H2h[(size_t)sA * 32 + lane];
        float eA = g_al2s[sA] + ald; eA = (eA > 0.f) ? eA : NEG * eA;
        float eeA = __expf(eA);
        denom += eeA;
        float2 vA = __half22float2(*reinterpret_cast<__half2*>(&pA));
        acc.x += eeA * vA.x; acc.y += eeA * vA.y;
    }

    float inv = 1.f / (denom + 1e-16f);
    float2 b = ((const float2*)b2)[lane];
    *(float2*)&out[(size_t)node * 64 + lane * 2] =
        make_float2(acc.x * inv + b.x, acc.y * inv + b.y);
}

// ---------------- launch ---------------------------------------------------
extern "C" void kernel_launch(void* const* d_in, const int* in_sizes, int n_in,
                              void* d_out, int out_size) {
    const float* x    = (const float*)d_in[0];
    const int*   ei   = (const int*)  d_in[1];
    const float* W1   = (const float*)d_in[2];
    const float* a1s  = (const float*)d_in[3];
    const float* a1d  = (const float*)d_in[4];
    const float* b1   = (const float*)d_in[5];
    const float* W2   = (const float*)d_in[6];
    const float* a2s  = (const float*)d_in[7];
    const float* a2d  = (const float*)d_in[8];
    const float* b2   = (const float*)d_in[9];
    float* out = (float*)d_out;

    int n  = in_sizes[0] / IN_C;
    int E  = in_sizes[1] / 2;
    int ET = E + n;

    float *pOUT1;
    int   *pCnt;
    cudaGetSymbolAddress((void**)&pOUT1, g_OUT1);
    cudaGetSymbolAddress((void**)&pCnt,  g_cnt);

    // CSR build (dst-sorted)
    cudaMemsetAsync(pCnt, 0, (size_t)n * sizeof(int));
    count_kernel  <<<(ET + 255) / 256, 256>>>(ei, E, ET);
    scan_kernel   <<<1, 1024>>>(n);
    scatter_kernel<<<(ET + 255) / 256, 256>>>(ei, E, ET);

    // layer 1
    const int SM1 = 128 * 128 * 4 + 64 * 128 * 4;  // 98304 B -> 2 blocks/SM
    cudaFuncSetAttribute((const void*)gemm1_kernel,
                         cudaFuncAttributeMaxDynamicSharedMemorySize, SM1);
    gemm1_kernel<<<(n + 63) / 64, 512, SM1>>>(x, W1, a1s, a1d, n);
    agg1_kernel<<<(n + 7) / 8, 256>>>(b1, n);

    // layer 2
    const int SM2 = 128 * 64 * 4 + 64 * 128 * 4;   // 65536 B -> 2 blocks/SM
    cudaFuncSetAttribute((const void*)gemm2_kernel,
                         cudaFuncAttributeMaxDynamicSharedMemorySize, SM2);
    gemm2_kernel<<<(n + 63) / 64, 512, SM2>>>(pOUT1, W2, a2s, a2d, n);
    agg2_kernel<<<(n + 7) / 8, 256>>>(b2, out, n);
}

// round 15
// speedup vs baseline: 1.1110x; 1.1110x over previous
#include <cuda_runtime.h>
#include <math.h>

#define NMAX   50000
#define EMAX   800000
#define ETMAX  (EMAX + NMAX)
#define IN_C   128
#define HID    16
#define HEADS  8
#define H1C    (HEADS * HID)   // 128
#define OUT_C  64
#define NEG    0.2f
#define CSRB   296             // scatter blocks fused ahead of gemm1 blocks

// ---------------- scratch (device globals; no allocation allowed) ----------
__device__ float g_H1[(size_t)NMAX * H1C];     // layer1 projected features
__device__ float g_OUT1[(size_t)NMAX * H1C];   // layer1 output (post relu)
__device__ float g_H2[(size_t)NMAX * OUT_C];   // layer2 projected features
__device__ float g_al1s[NMAX * HEADS];
__device__ float g_al1d[NMAX * HEADS];
__device__ float g_al2s[NMAX];
__device__ float g_al2d[NMAX];
__device__ int   g_rowptr[NMAX + 1];
__device__ int   g_cnt[NMAX];                  // counts, then write cursors
__device__ int   g_esrc[ETMAX];                // src node per (dst-sorted) edge

// ---------------- CSR build ------------------------------------------------
__global__ void count_kernel(const int* __restrict__ ei, int E, int ET) {
    int i = blockIdx.x * blockDim.x + threadIdx.x;
    if (i >= ET) return;
    int dst = (i < E) ? ei[E + i] : (i - E);   // self loops appended
    atomicAdd(&g_cnt[dst], 1);
}

// single-block scan, 2 barriers: serial partials + two-level shuffle scan
__global__ void scan_kernel(int n) {
    const int T = 1024;
    __shared__ int wsum[32];
    int t = threadIdx.x, lane = t & 31, wid = t >> 5;
    int C = (n + T - 1) / T;
    int beg = t * C;
    int end = beg + C; if (end > n) end = n;

    int sum = 0;
    for (int i = beg; i < end; i++) sum += g_cnt[i];

    int incl = sum;
#pragma unroll
    for (int off = 1; off < 32; off <<= 1) {
        int v = __shfl_up_sync(0xffffffffu, incl, off);
        if (lane >= off) incl += v;
    }
    if (lane == 31) wsum[wid] = incl;
    __syncthreads();
    if (wid == 0) {
        int w = wsum[lane];
        int wi = w;
#pragma unroll
        for (int off = 1; off < 32; off <<= 1) {
            int v = __shfl_up_sync(0xffffffffu, wi, off);
            if (lane >= off) wi += v;
        }
        wsum[lane] = wi - w;
    }
    __syncthreads();

    int run = wsum[wid] + (incl - sum);
    for (int i = beg; i < end; i++) {
        int c = g_cnt[i];
        g_rowptr[i] = run;
        g_cnt[i]    = run;
        run += c;
    }
    if (beg < n && end == n) g_rowptr[n] = run;
}

// ---------------- fused: scatter (blocks [0,CSRB)) | gemm1 (rest) ----------
// gemm1: H1 = X @ W1, fused al1 logits. 512 thr, 64 rows x 128 cols,
// smem 96KB -> 2 blocks/SM. Scatter blocks issued first, co-resident with
// gemm1 blocks -> scatter cost hidden under the GEMM.
__global__ __launch_bounds__(512, 2) void gemm1_scatter_kernel(
        const float* __restrict__ X, const float* __restrict__ W,
        const float* __restrict__ a1s, const float* __restrict__ a1d,
        const int* __restrict__ ei, int E, int ET, int M) {
    if (blockIdx.x < CSRB) {
        // scatter: build dst-sorted edge list (grid-stride)
        for (int i = blockIdx.x * 512 + threadIdx.x; i < ET; i += CSRB * 512) {
            int src, dst;
            if (i < E) { src = ei[i]; dst = ei[E + i]; }
            else       { src = i - E; dst = i - E; }
            int pos = atomicAdd(&g_cnt[dst], 1);
            g_esrc[pos] = src;
        }
        return;
    }
    extern __shared__ float smem[];
    float4* Wsh = (float4*)smem;           // 128 * 32 float4 = 64 KB
    float*  Xsh = smem + 128 * 128;        // 64 * 128 floats = 32 KB
    int tid = threadIdx.x;

    const float4* W4 = (const float4*)W;
    for (int i = tid; i < 128 * 32; i += 512) Wsh[i] = W4[i];

    int row0 = (blockIdx.x - CSRB) * 64;
    for (int i = tid; i < 64 * 32; i += 512) {
        int r = i >> 5, kc = i & 31;
        float4 v = make_float4(0.f, 0.f, 0.f, 0.f);
        if (row0 + r < M) v = ((const float4*)X)[(size_t)(row0 + r) * 32 + kc];
        *(float4*)&Xsh[r * 128 + kc * 4] = v;
    }
    __syncthreads();

    int tx = tid & 31, ty = tid >> 5;      // warp == ty
    float4 acc[4];
#pragma unroll
    for (int r = 0; r < 4; r++) acc[r] = make_float4(0.f, 0.f, 0.f, 0.f);

    for (int k4 = 0; k4 < 32; k4++) {
        float4 wv0 = Wsh[(k4 * 4 + 0) * 32 + tx];
        float4 wv1 = Wsh[(k4 * 4 + 1) * 32 + tx];
        float4 wv2 = Wsh[(k4 * 4 + 2) * 32 + tx];
        float4 wv3 = Wsh[(k4 * 4 + 3) * 32 + tx];
#pragma unroll
        for (int r = 0; r < 4; r++) {
            float4 xv = *(const float4*)&Xsh[(ty * 4 + r) * 128 + k4 * 4];
            acc[r].x += xv.x * wv0.x + xv.y * wv1.x + xv.z * wv2.x + xv.w * wv3.x;
            acc[r].y += xv.x * wv0.y + xv.y * wv1.y + xv.z * wv2.y + xv.w * wv3.y;
            acc[r].z += xv.x * wv0.z + xv.y * wv1.z + xv.z * wv2.z + xv.w * wv3.z;
            acc[r].w += xv.x * wv0.w + xv.y * wv1.w + xv.z * wv2.w + xv.w * wv3.w;
        }
    }

    float4 as = ((const float4*)a1s)[tx];
    float4 ad = ((const float4*)a1d)[tx];
    int head = tx >> 2;
#pragma unroll
    for (int r = 0; r < 4; r++) {
        int row = row0 + ty * 4 + r;
        if (row < M) {
            ((float4*)g_H1)[(size_t)row * 32 + tx] = acc[r];
            float ps = acc[r].x * as.x + acc[r].y * as.y + acc[r].z * as.z + acc[r].w * as.w;
            float pd = acc[r].x * ad.x + acc[r].y * ad.y + acc[r].z * ad.z + acc[r].w * ad.w;
            ps += __shfl_xor_sync(0xffffffffu, ps, 1);
            ps += __shfl_xor_sync(0xffffffffu, ps, 2);
            pd += __shfl_xor_sync(0xffffffffu, pd, 1);
            pd += __shfl_xor_sync(0xffffffffu, pd, 2);
            if ((tx & 3) == 0) {
                g_al1s[row * 8 + head] = ps;
                g_al1d[row * 8 + head] = pd;
            }
        }
    }
}

// ---------------- GEMM2: H2 = OUT1 @ W2, fused al2 logits ------------------
// 512 thr, 128 rows x 64 cols per block; 4 rows/thread -> same FMA/LDS
// density as gemm1. smem 96KB -> 2 blocks/SM.
__global__ __launch_bounds__(512, 2) void gemm2_kernel(
        const float* __restrict__ X, const float* __restrict__ W,
        const float* __restrict__ a2s, const float* __restrict__ a2d, int M) {
    extern __shared__ float smem[];
    float4* Wsh = (float4*)smem;           // 128 * 16 float4 = 32 KB
    float*  Xsh = smem + 128 * 64;         // 128 * 128 floats = 64 KB
    int tid = threadIdx.x;

    const float4* W4 = (const float4*)W;
    for (int i = tid; i < 128 * 16; i += 512) Wsh[i] = W4[i];

    int row0 = blockIdx.x * 128;
    for (int i = tid; i < 128 * 32; i += 512) {
        int r = i >> 5, kc = i & 31;
        float4 v = make_float4(0.f, 0.f, 0.f, 0.f);
        if (row0 + r < M) v = ((const float4*)X)[(size_t)(row0 + r) * 32 + kc];
        *(float4*)&Xsh[r * 128 + kc * 4] = v;
    }
    __syncthreads();

    int tx = tid & 15, ty = tid >> 4;      // 32 row-groups, 4 rows each
    float4 acc[4];
#pragma unroll
    for (int r = 0; r < 4; r++) acc[r] = make_float4(0.f, 0.f, 0.f, 0.f);

    for (int k4 = 0; k4 < 32; k4++) {
        float4 wv0 = Wsh[(k4 * 4 + 0) * 16 + tx];
        float4 wv1 = Wsh[(k4 * 4 + 1) * 16 + tx];
        float4 wv2 = Wsh[(k4 * 4 + 2) * 16 + tx];
        float4 wv3 = Wsh[(k4 * 4 + 3) * 16 + tx];
#pragma unroll
        for (int r = 0; r < 4; r++) {
            float4 xv = *(const float4*)&Xsh[(ty * 4 + r) * 128 + k4 * 4];
            acc[r].x += xv.x * wv0.x + xv.y * wv1.x + xv.z * wv2.x + xv.w * wv3.x;
            acc[r].y += xv.x * wv0.y + xv.y * wv1.y + xv.z * wv2.y + xv.w * wv3.y;
            acc[r].z += xv.x * wv0.z + xv.y * wv1.z + xv.z * wv2.z + xv.w * wv3.z;
            acc[r].w += xv.x * wv0.w + xv.y * wv1.w + xv.z * wv2.w + xv.w * wv3.w;
        }
    }

    float4 as = ((const float4*)a2s)[tx];
    float4 ad = ((const float4*)a2d)[tx];
#pragma unroll
    for (int r = 0; r < 4; r++) {
        int row = row0 + ty * 4 + r;
        if (row < M) {
            ((float4*)g_H2)[(size_t)row * 16 + tx] = acc[r];
            float ps = acc[r].x * as.x + acc[r].y * as.y + acc[r].z * as.z + acc[r].w * as.w;
            float pd = acc[r].x * ad.x + acc[r].y * ad.y + acc[r].z * ad.z + acc[r].w * ad.w;
#pragma unroll
            for (int off = 8; off >= 1; off >>= 1) {   // reduce within 16-lane group
                ps += __shfl_xor_sync(0xffffffffu, ps, off);
                pd += __shfl_xor_sync(0xffffffffu, pd, off);
            }
            if (tx == 0) { g_al2s[row] = ps; g_al2d[row] = pd; }
        }
    }
}

// ---------------- aggregation: single pass, pairwise (MLP=2) ---------------
// Logits are O(1): exp without max subtraction is overflow-safe and exact.
__global__ void agg1_kernel(const float* __restrict__ b1, int n) {
    int node = (blockIdx.x * blockDim.x + threadIdx.x) >> 5;
    int lane = threadIdx.x & 31;
    if (node >= n) return;
    int beg = g_rowptr[node], end = g_rowptr[node + 1];
    float ald = (lane < 8) ? g_al1d[node * 8 + lane] : 0.f;
    int head = lane >> 2;

    float denom = 0.f;
    float4 acc = make_float4(0.f, 0.f, 0.f, 0.f);

    int sA = (beg     < end) ? g_esrc[beg]     : 0;
    int sB = (beg + 1 < end) ? g_esrc[beg + 1] : 0;
    int j = beg;
    for (; j + 1 < end; j += 2) {
        int sC = (j + 2 < end) ? g_esrc[j + 2] : 0;
        int sD = (j + 3 < end) ? g_esrc[j + 3] : 0;
        float4 vA = *(const float4*)&g_H1[(size_t)sA * 128 + lane * 4];
        float4 vB = *(const float4*)&g_H1[(size_t)sB * 128 + lane * 4];
        float eeA = 0.f, eeB = 0.f;
        if (lane < 8) {
            float lA = g_al1s[sA * 8 + lane];
            float lB = g_al1s[sB * 8 + lane];
            float eA = lA + ald; eA = (eA > 0.f) ? eA : NEG * eA;
            float eB = lB + ald; eB = (eB > 0.f) ? eB : NEG * eB;
            eeA = __expf(eA); eeB = __expf(eB);
            denom += eeA + eeB;
        }
        float wA = __shfl_sync(0xffffffffu, eeA, head);
        float wB = __shfl_sync(0xffffffffu, eeB, head);
        acc.x += wA * vA.x + wB * vB.x;
        acc.y += wA * vA.y + wB * vB.y;
        acc.z += wA * vA.z + wB * vB.z;
        acc.w += wA * vA.w + wB * vB.w;
        sA = sC; sB = sD;
    }
    if (j < end) {   // odd tail: sA holds esrc[j]
        float4 vA = *(const float4*)&g_H1[(size_t)sA * 128 + lane * 4];
        float eeA = 0.f;
        if (lane < 8) {
            float eA = g_al1s[sA * 8 + lane] + ald;
            eA = (eA > 0.f) ? eA : NEG * eA;
            eeA = __expf(eA);
            denom += eeA;
        }
        float wA = __shfl_sync(0xffffffffu, eeA, head);
        acc.x += wA * vA.x; acc.y += wA * vA.y;
        acc.z += wA * vA.z; acc.w += wA * vA.w;
    }

    float dh  = __shfl_sync(0xffffffffu, denom, head);
    float inv = 1.f / (dh + 1e-16f);
    float4 b = ((const float4*)b1)[lane];
    float4 o;
    o.x = fmaxf(acc.x * inv + b.x, 0.f);
    o.y = fmaxf(acc.y * inv + b.y, 0.f);
    o.z = fmaxf(acc.z * inv + b.z, 0.f);
    o.w = fmaxf(acc.w * inv + b.w, 0.f);
    *(float4*)&g_OUT1[(size_t)node * 128 + lane * 4] = o;
}

__global__ void agg2_kernel(const float* __restrict__ b2,
                            float* __restrict__ out, int n) {
    int node = (blockIdx.x * blockDim.x + threadIdx.x) >> 5;
    int lane = threadIdx.x & 31;
    if (node >= n) return;
    int beg = g_rowptr[node], end = g_rowptr[node + 1];
    float ald = g_al2d[node];

    float denom = 0.f;
    float2 acc = make_float2(0.f, 0.f);

    int sA = (beg     < end) ? g_esrc[beg]     : 0;
    int sB = (beg + 1 < end) ? g_esrc[beg + 1] : 0;
    int j = beg;
    for (; j + 1 < end; j += 2) {
        int sC = (j + 2 < end) ? g_esrc[j + 2] : 0;
        int sD = (j + 3 < end) ? g_esrc[j + 3] : 0;
        float2 vA = *(const float2*)&g_H2[(size_t)sA * 64 + lane * 2];
        float2 vB = *(const float2*)&g_H2[(size_t)sB * 64 + lane * 2];
        float eA = g_al2s[sA] + ald; eA = (eA > 0.f) ? eA : NEG * eA;
        float eB = g_al2s[sB] + ald; eB = (eB > 0.f) ? eB : NEG * eB;
        float eeA = __expf(eA), eeB = __expf(eB);
        denom += eeA + eeB;
        acc.x += eeA * vA.x + eeB * vB.x;
        acc.y += eeA * vA.y + eeB * vB.y;
        sA = sC; sB = sD;
    }
    if (j < end) {
        float2 vA = *(const float2*)&g_H2[(size_t)sA * 64 + lane * 2];
        float eA = g_al2s[sA] + ald; eA = (eA > 0.f) ? eA : NEG * eA;
        float eeA = __expf(eA);
        denom += eeA;
        acc.x += eeA * vA.x; acc.y += eeA * vA.y;
    }

    float inv = 1.f / (denom + 1e-16f);
    float2 b = ((const float2*)b2)[lane];
    *(float2*)&out[(size_t)node * 64 + lane * 2] =
        make_float2(acc.x * inv + b.x, acc.y * inv + b.y);
}

// ---------------- launch ---------------------------------------------------
extern "C" void kernel_launch(void* const* d_in, const int* in_sizes, int n_in,
                              void* d_out, int out_size) {
    const float* x    = (const float*)d_in[0];
    const int*   ei   = (const int*)  d_in[1];
    const float* W1   = (const float*)d_in[2];
    const float* a1s  = (const float*)d_in[3];
    const float* a1d  = (const float*)d_in[4];
    const float* b1   = (const float*)d_in[5];
    const float* W2   = (const float*)d_in[6];
    const float* a2s  = (const float*)d_in[7];
    const float* a2d  = (const float*)d_in[8];
    const float* b2   = (const float*)d_in[9];
    float* out = (float*)d_out;

    int n  = in_sizes[0] / IN_C;
    int E  = in_sizes[1] / 2;
    int ET = E + n;

    float *pOUT1;
    int   *pCnt;
    cudaGetSymbolAddress((void**)&pOUT1, g_OUT1);
    cudaGetSymbolAddress((void**)&pCnt,  g_cnt);

    // CSR count + scan (scatter is fused into the gemm1 launch below)
    cudaMemsetAsync(pCnt, 0, (size_t)n * sizeof(int));
    count_kernel<<<(ET + 255) / 256, 256>>>(ei, E, ET);
    scan_kernel <<<1, 1024>>>(n);

    // layer 1: fused scatter | gemm1
    const int SM1 = 128 * 128 * 4 + 64 * 128 * 4;  // 98304 B -> 2 blocks/SM
    cudaFuncSetAttribute((const void*)gemm1_scatter_kernel,
                         cudaFuncAttributeMaxDynamicSharedMemorySize, SM1);
    int g1 = CSRB + (n + 63) / 64;
    gemm1_scatter_kernel<<<g1, 512, SM1>>>(x, W1, a1s, a1d, ei, E, ET, n);
    agg1_kernel<<<(n + 7) / 8, 256>>>(b1, n);

    // layer 2
    const int SM2 = 128 * 64 * 4 + 128 * 128 * 4;  // 98304 B -> 2 blocks/SM
    cudaFuncSetAttribute((const void*)gemm2_kernel,
                         cudaFuncAttributeMaxDynamicSharedMemorySize, SM2);
    gemm2_kernel<<<(n + 127) / 128, 512, SM2>>>(pOUT1, W2, a2s, a2d, n);
    agg2_kernel<<<(n + 7) / 8, 256>>>(b2, out, n);
}

// round 16
// speedup vs baseline: 1.1675x; 1.0508x over previous
#include <cuda_runtime.h>
#include <math.h>

#define NMAX   50000
#define EMAX   800000
#define ETMAX  (EMAX + NMAX)
#define IN_C   128
#define HID    16
#define HEADS  8
#define H1C    (HEADS * HID)   // 128
#define OUT_C  64
#define NEG    0.2f
#define CSRB   64              // CSR blocks fused ahead of gemm1 blocks

// ---------------- scratch (device globals; no allocation allowed) ----------
__device__ float g_H1[(size_t)NMAX * H1C];     // layer1 projected features
__device__ float g_OUT1[(size_t)NMAX * H1C];   // layer1 output (post relu)
__device__ float g_H2[(size_t)NMAX * OUT_C];   // layer2 projected features
__device__ float g_al1s[NMAX * HEADS];
__device__ float g_al1d[NMAX * HEADS];
__device__ float g_al2s[NMAX];
__device__ float g_al2d[NMAX];
__device__ int   g_rowptr[NMAX + 1];
__device__ int   g_cnt[NMAX];                  // counts, then write cursors
__device__ int   g_esrc[ETMAX];                // src node per (dst-sorted) edge
__device__ int   g_bar;                        // CSR spin barrier (memset to 0)

// ---------------- CSR barrier (among the CSRB co-resident blocks) ----------
__device__ __forceinline__ void csr_barrier(int target) {
    __threadfence();
    __syncthreads();
    if (threadIdx.x == 0) {
        atomicAdd(&g_bar, 1);
        while (*(volatile int*)&g_bar < target) { }
        __threadfence();
    }
    __syncthreads();
}

// ---------------- fused: CSR build (blocks [0,CSRB)) | gemm1 (rest) --------
// CSR: count -> barrier -> scan(block 0) -> barrier -> scatter.
// gemm1: H1 = X @ W1, fused al1 logits. 512 thr, 64 rows x 128 cols,
// smem 96KB -> 2 blocks/SM; CSRB=64 < 296 first-wave slots => all CSR blocks
// co-resident (spin barrier is deadlock-free), cost hidden under the GEMM.
__global__ __launch_bounds__(512, 2) void gemm1_csr_kernel(
        const float* __restrict__ X, const float* __restrict__ W,
        const float* __restrict__ a1s, const float* __restrict__ a1d,
        const int* __restrict__ ei, int E, int ET, int M) {
    if (blockIdx.x < CSRB) {
        int tid = threadIdx.x;
        // phase 1: count degrees (g_cnt zeroed by host memset)
        for (int i = blockIdx.x * 512 + tid; i < ET; i += CSRB * 512) {
            int dst = (i < E) ? ei[E + i] : (i - E);   // self loops appended
            atomicAdd(&g_cnt[dst], 1);
        }
        csr_barrier(CSRB);
        // phase 2: exclusive scan (block 0 only; 512 thr serial partials +
        // two-level shuffle scan)
        if (blockIdx.x == 0) {
            __shared__ int wsum[16];
            int lane = tid & 31, wid = tid >> 5;
            int C = (M + 511) / 512;
            int beg = tid * C;
            int end = beg + C; if (end > M) end = M;
            int sum = 0;
            for (int i = beg; i < end; i++) sum += g_cnt[i];
            int incl = sum;
#pragma unroll
            for (int off = 1; off < 32; off <<= 1) {
                int v = __shfl_up_sync(0xffffffffu, incl, off);
                if (lane >= off) incl += v;
            }
            if (lane == 31) wsum[wid] = incl;
            __syncthreads();
            if (wid == 0) {
                int w = (lane < 16) ? wsum[lane] : 0;
                int wi = w;
#pragma unroll
                for (int off = 1; off < 16; off <<= 1) {
                    int v = __shfl_up_sync(0xffffffffu, wi, off);
                    if (lane >= off) wi += v;
                }
                if (lane < 16) wsum[lane] = wi - w;   // exclusive warp base
            }
            __syncthreads();
            int run = wsum[wid] + (incl - sum);
            for (int i = beg; i < end; i++) {
                int c = g_cnt[i];
                g_rowptr[i] = run;
                g_cnt[i]    = run;
                run += c;
            }
            if (beg < M && end == M) g_rowptr[M] = run;
        }
        csr_barrier(2 * CSRB);
        // phase 3: scatter into dst-sorted edge list
        for (int i = blockIdx.x * 512 + tid; i < ET; i += CSRB * 512) {
            int src, dst;
            if (i < E) { src = ei[i]; dst = ei[E + i]; }
            else       { src = i - E; dst = i - E; }
            int pos = atomicAdd(&g_cnt[dst], 1);
            g_esrc[pos] = src;
        }
        return;
    }
    extern __shared__ float smem[];
    float4* Wsh = (float4*)smem;           // 128 * 32 float4 = 64 KB
    float*  Xsh = smem + 128 * 128;        // 64 * 128 floats = 32 KB
    int tid = threadIdx.x;

    const float4* W4 = (const float4*)W;
    for (int i = tid; i < 128 * 32; i += 512) Wsh[i] = W4[i];

    int row0 = (blockIdx.x - CSRB) * 64;
    for (int i = tid; i < 64 * 32; i += 512) {
        int r = i >> 5, kc = i & 31;
        float4 v = make_float4(0.f, 0.f, 0.f, 0.f);
        if (row0 + r < M) v = ((const float4*)X)[(size_t)(row0 + r) * 32 + kc];
        *(float4*)&Xsh[r * 128 + kc * 4] = v;
    }
    __syncthreads();

    int tx = tid & 31, ty = tid >> 5;      // warp == ty
    float4 acc[4];
#pragma unroll
    for (int r = 0; r < 4; r++) acc[r] = make_float4(0.f, 0.f, 0.f, 0.f);

    for (int k4 = 0; k4 < 32; k4++) {
        float4 wv0 = Wsh[(k4 * 4 + 0) * 32 + tx];
        float4 wv1 = Wsh[(k4 * 4 + 1) * 32 + tx];
        float4 wv2 = Wsh[(k4 * 4 + 2) * 32 + tx];
        float4 wv3 = Wsh[(k4 * 4 + 3) * 32 + tx];
#pragma unroll
        for (int r = 0; r < 4; r++) {
            float4 xv = *(const float4*)&Xsh[(ty * 4 + r) * 128 + k4 * 4];
            acc[r].x += xv.x * wv0.x + xv.y * wv1.x + xv.z * wv2.x + xv.w * wv3.x;
            acc[r].y += xv.x * wv0.y + xv.y * wv1.y + xv.z * wv2.y + xv.w * wv3.y;
            acc[r].z += xv.x * wv0.z + xv.y * wv1.z + xv.z * wv2.z + xv.w * wv3.z;
            acc[r].w += xv.x * wv0.w + xv.y * wv1.w + xv.z * wv2.w + xv.w * wv3.w;
        }
    }

    float4 as = ((const float4*)a1s)[tx];
    float4 ad = ((const float4*)a1d)[tx];
    int head = tx >> 2;
#pragma unroll
    for (int r = 0; r < 4; r++) {
        int row = row0 + ty * 4 + r;
        if (row < M) {
            ((float4*)g_H1)[(size_t)row * 32 + tx] = acc[r];
            float ps = acc[r].x * as.x + acc[r].y * as.y + acc[r].z * as.z + acc[r].w * as.w;
            float pd = acc[r].x * ad.x + acc[r].y * ad.y + acc[r].z * ad.z + acc[r].w * ad.w;
            ps += __shfl_xor_sync(0xffffffffu, ps, 1);
            ps += __shfl_xor_sync(0xffffffffu, ps, 2);
            pd += __shfl_xor_sync(0xffffffffu, pd, 1);
            pd += __shfl_xor_sync(0xffffffffu, pd, 2);
            if ((tx & 3) == 0) {
                g_al1s[row * 8 + head] = ps;
                g_al1d[row * 8 + head] = pd;
            }
        }
    }
}

// ---------------- GEMM2: H2 = OUT1 @ W2, fused al2 logits ------------------
// 512 thr, 128 rows x 64 cols per block; 4 rows/thread. smem 96KB.
__global__ __launch_bounds__(512, 2) void gemm2_kernel(
        const float* __restrict__ X, const float* __restrict__ W,
        const float* __restrict__ a2s, const float* __restrict__ a2d, int M) {
    extern __shared__ float smem[];
    float4* Wsh = (float4*)smem;           // 128 * 16 float4 = 32 KB
    float*  Xsh = smem + 128 * 64;         // 128 * 128 floats = 64 KB
    int tid = threadIdx.x;

    const float4* W4 = (const float4*)W;
    for (int i = tid; i < 128 * 16; i += 512) Wsh[i] = W4[i];

    int row0 = blockIdx.x * 128;
    for (int i = tid; i < 128 * 32; i += 512) {
        int r = i >> 5, kc = i & 31;
        float4 v = make_float4(0.f, 0.f, 0.f, 0.f);
        if (row0 + r < M) v = ((const float4*)X)[(size_t)(row0 + r) * 32 + kc];
        *(float4*)&Xsh[r * 128 + kc * 4] = v;
    }
    __syncthreads();

    int tx = tid & 15, ty = tid >> 4;      // 32 row-groups, 4 rows each
    float4 acc[4];
#pragma unroll
    for (int r = 0; r < 4; r++) acc[r] = make_float4(0.f, 0.f, 0.f, 0.f);

    for (int k4 = 0; k4 < 32; k4++) {
        float4 wv0 = Wsh[(k4 * 4 + 0) * 16 + tx];
        float4 wv1 = Wsh[(k4 * 4 + 1) * 16 + tx];
        float4 wv2 = Wsh[(k4 * 4 + 2) * 16 + tx];
        float4 wv3 = Wsh[(k4 * 4 + 3) * 16 + tx];
#pragma unroll
        for (int r = 0; r < 4; r++) {
            float4 xv = *(const float4*)&Xsh[(ty * 4 + r) * 128 + k4 * 4];
            acc[r].x += xv.x * wv0.x + xv.y * wv1.x + xv.z * wv2.x + xv.w * wv3.x;
            acc[r].y += xv.x * wv0.y + xv.y * wv1.y + xv.z * wv2.y + xv.w * wv3.y;
            acc[r].z += xv.x * wv0.z + xv.y * wv1.z + xv.z * wv2.z + xv.w * wv3.z;
            acc[r].w += xv.x * wv0.w + xv.y * wv1.w + xv.z * wv2.w + xv.w * wv3.w;
        }
    }

    float4 as = ((const float4*)a2s)[tx];
    float4 ad = ((const float4*)a2d)[tx];
#pragma unroll
    for (int r = 0; r < 4; r++) {
        int row = row0 + ty * 4 + r;
        if (row < M) {
            ((float4*)g_H2)[(size_t)row * 16 + tx] = acc[r];
            float ps = acc[r].x * as.x + acc[r].y * as.y + acc[r].z * as.z + acc[r].w * as.w;
            float pd = acc[r].x * ad.x + acc[r].y * ad.y + acc[r].z * ad.z + acc[r].w * ad.w;
#pragma unroll
            for (int off = 8; off >= 1; off >>= 1) {   // reduce within 16-lane group
                ps += __shfl_xor_sync(0xffffffffu, ps, off);
                pd += __shfl_xor_sync(0xffffffffu, pd, off);
            }
            if (tx == 0) { g_al2s[row] = ps; g_al2d[row] = pd; }
        }
    }
}

// ---------------- aggregation: pairwise (MLP=2), shuffle-free --------------
// Every lane computes the logit/exp for its OWN head (al1s[s*8 + lane>>2]):
// same 32B broadcast sector, and since predicated-off lanes would issue the
// exp chain anyway, the redundancy is free -- it deletes all shuffles.
// Logits are O(1): exp without max subtraction is overflow-safe and exact.
__global__ void agg1_kernel(const float* __restrict__ b1, int n) {
    int node = (blockIdx.x * blockDim.x + threadIdx.x) >> 5;
    int lane = threadIdx.x & 31;
    if (node >= n) return;
    int beg = g_rowptr[node], end = g_rowptr[node + 1];
    int head = lane >> 2;
    float ald = g_al1d[node * 8 + head];

    float denom = 0.f;                     // head-uniform across its 4 lanes
    float4 acc = make_float4(0.f, 0.f, 0.f, 0.f);

    int sA = (beg     < end) ? g_esrc[beg]     : 0;
    int sB = (beg + 1 < end) ? g_esrc[beg + 1] : 0;
    int j = beg;
    for (; j + 1 < end; j += 2) {
        int sC = (j + 2 < end) ? g_esrc[j + 2] : 0;
        int sD = (j + 3 < end) ? g_esrc[j + 3] : 0;
        float4 vA = *(const float4*)&g_H1[(size_t)sA * 128 + lane * 4];
        float4 vB = *(const float4*)&g_H1[(size_t)sB * 128 + lane * 4];
        float lA = g_al1s[sA * 8 + head];
        float lB = g_al1s[sB * 8 + head];
        float eA = lA + ald; eA = (eA > 0.f) ? eA : NEG * eA;
        float eB = lB + ald; eB = (eB > 0.f) ? eB : NEG * eB;
        float eeA = __expf(eA), eeB = __expf(eB);
        denom += eeA + eeB;
        acc.x += eeA * vA.x + eeB * vB.x;
        acc.y += eeA * vA.y + eeB * vB.y;
        acc.z += eeA * vA.z + eeB * vB.z;
        acc.w += eeA * vA.w + eeB * vB.w;
        sA = sC; sB = sD;
    }
    if (j < end) {   // odd tail: sA holds esrc[j]
        float4 vA = *(const float4*)&g_H1[(size_t)sA * 128 + lane * 4];
        float eA = g_al1s[sA * 8 + head] + ald;
        eA = (eA > 0.f) ? eA : NEG * eA;
        float eeA = __expf(eA);
        denom += eeA;
        acc.x += eeA * vA.x; acc.y += eeA * vA.y;
        acc.z += eeA * vA.z; acc.w += eeA * vA.w;
    }

    float inv = 1.f / (denom + 1e-16f);
    float4 b = ((const float4*)b1)[lane];
    float4 o;
    o.x = fmaxf(acc.x * inv + b.x, 0.f);
    o.y = fmaxf(acc.y * inv + b.y, 0.f);
    o.z = fmaxf(acc.z * inv + b.z, 0.f);
    o.w = fmaxf(acc.w * inv + b.w, 0.f);
    *(float4*)&g_OUT1[(size_t)node * 128 + lane * 4] = o;
}

__global__ void agg2_kernel(const float* __restrict__ b2,
                            float* __restrict__ out, int n) {
    int node = (blockIdx.x * blockDim.x + threadIdx.x) >> 5;
    int lane = threadIdx.x & 31;
    if (node >= n) return;
    int beg = g_rowptr[node], end = g_rowptr[node + 1];
    float ald = g_al2d[node];

    float denom = 0.f;
    float2 acc = make_float2(0.f, 0.f);

    int sA = (beg     < end) ? g_esrc[beg]     : 0;
    int sB = (beg + 1 < end) ? g_esrc[beg + 1] : 0;
    int j = beg;
    for (; j + 1 < end; j += 2) {
        int sC = (j + 2 < end) ? g_esrc[j + 2] : 0;
        int sD = (j + 3 < end) ? g_esrc[j + 3] : 0;
        float2 vA = *(const float2*)&g_H2[(size_t)sA * 64 + lane * 2];
        float2 vB = *(const float2*)&g_H2[(size_t)sB * 64 + lane * 2];
        float eA = g_al2s[sA] + ald; eA = (eA > 0.f) ? eA : NEG * eA;
        float eB = g_al2s[sB] + ald; eB = (eB > 0.f) ? eB : NEG * eB;
        float eeA = __expf(eA), eeB = __expf(eB);
        denom += eeA + eeB;
        acc.x += eeA * vA.x + eeB * vB.x;
        acc.y += eeA * vA.y + eeB * vB.y;
        sA = sC; sB = sD;
    }
    if (j < end) {
        float2 vA = *(const float2*)&g_H2[(size_t)sA * 64 + lane * 2];
        float eA = g_al2s[sA] + ald; eA = (eA > 0.f) ? eA : NEG * eA;
        float eeA = __expf(eA);
        denom += eeA;
        acc.x += eeA * vA.x; acc.y += eeA * vA.y;
    }

    float inv = 1.f / (denom + 1e-16f);
    float2 b = ((const float2*)b2)[lane];
    *(float2*)&out[(size_t)node * 64 + lane * 2] =
        make_float2(acc.x * inv + b.x, acc.y * inv + b.y);
}

// ---------------- launch ---------------------------------------------------
extern "C" void kernel_launch(void* const* d_in, const int* in_sizes, int n_in,
                              void* d_out, int out_size) {
    const float* x    = (const float*)d_in[0];
    const int*   ei   = (const int*)  d_in[1];
    const float* W1   = (const float*)d_in[2];
    const float* a1s  = (const float*)d_in[3];
    const float* a1d  = (const float*)d_in[4];
    const float* b1   = (const float*)d_in[5];
    const float* W2   = (const float*)d_in[6];
    const float* a2s  = (const float*)d_in[7];
    const float* a2d  = (const float*)d_in[8];
    const float* b2   = (const float*)d_in[9];
    float* out = (float*)d_out;

    int n  = in_sizes[0] / IN_C;
    int E  = in_sizes[1] / 2;
    int ET = E + n;

    float *pOUT1;
    int   *pCnt, *pBar;
    cudaGetSymbolAddress((void**)&pOUT1, g_OUT1);
    cudaGetSymbolAddress((void**)&pCnt,  g_cnt);
    cudaGetSymbolAddress((void**)&pBar,  g_bar);

    // zero counters (CSR build itself is fused into the gemm1 launch)
    cudaMemsetAsync(pCnt, 0, (size_t)n * sizeof(int));
    cudaMemsetAsync(pBar, 0, sizeof(int));

    // layer 1: fused CSR | gemm1
    const int SM1 = 128 * 128 * 4 + 64 * 128 * 4;  // 98304 B -> 2 blocks/SM
    cudaFuncSetAttribute((const void*)gemm1_csr_kernel,
                         cudaFuncAttributeMaxDynamicSharedMemorySize, SM1);
    int g1 = CSRB + (n + 63) / 64;
    gemm1_csr_kernel<<<g1, 512, SM1>>>(x, W1, a1s, a1d, ei, E, ET, n);
    agg1_kernel<<<(n + 7) / 8, 256>>>(b1, n);

    // layer 2
    const int SM2 = 128 * 64 * 4 + 128 * 128 * 4;  // 98304 B -> 2 blocks/SM
    cudaFuncSetAttribute((const void*)gemm2_kernel,
                         cudaFuncAttributeMaxDynamicSharedMemorySize, SM2);
    gemm2_kernel<<<(n + 127) / 128, 512, SM2>>>(pOUT1, W2, a2s, a2d, n);
    agg2_kernel<<<(n + 7) / 8, 256>>>(b2, out, n);
}